// round 14
// baseline (speedup 1.0000x reference)
#include <cuda_runtime.h>
#include <cstddef>
#include <cstdint>

// RoutingByAgreement: x[B,64,64] f32 -> v[B,64] f32, 3 iterations.
// ONE WARP PER BATCH, zero __syncthreads. 128-thread CTAs, 3 CTAs/SM.
// Lane l owns columns 2l, 2l+1: float2 xc[64] in registers.
// Agreement = TWO sequential half-butterflies (rows 0-31, 32-63), each with
// peak red[16] live -> ~16 fewer peak registers than the single red[32]
// butterfly (kills the spill pressure at the (128,3) 170-reg cap).
// Lane's rows: rA = bitrev5(l) and rA+32.

#define FULLMASK 0xffffffffu

static __device__ __forceinline__ float frcp(float x) {
    float r; asm("rcp.approx.f32 %0, %1;" : "=f"(r) : "f"(x)); return r;
}
static __device__ __forceinline__ float frsq(float x) {
    float r; asm("rsqrt.approx.f32 %0, %1;" : "=f"(r) : "f"(x)); return r;
}

__global__ void __launch_bounds__(128, 3)
routing_kernel(const float* __restrict__ x, float* __restrict__ out, int B)
{
    __shared__ __align__(16) float se[4][64];   // per-warp softmax strip

    const int t = threadIdx.x;
    const int wid = t >> 5, l = t & 31;
    float* __restrict__ sew = se[wid];

    const int gwarp = blockIdx.x * 4 + wid;
    const int nwarps = gridDim.x * 4;

    // half-butterfly output row: rA = bitrev5(l); other row = rA + 32
    const int rA = ((l & 1) << 4) | ((l & 2) << 2) | (l & 4)
                 | ((l & 8) >> 2) | ((l & 16) >> 4);

    for (int b = gwarp; b < B; b += nwarps) {
        const float* __restrict__ xb = x + (size_t)b * 4096 + 2 * l;

        // ---- load tile: 64 coalesced LDG.64 per lane ----
        float2 xc[64];
#pragma unroll
        for (int n = 0; n < 64; n++)
            xc[n] = *reinterpret_cast<const float2*>(xb + n * 64);

        // ---- prefetch next batch into L2 (4 x 128B lines per lane) ----
        {
            const int bn = b + nwarps;
            if (bn < B) {
                const char* pf = (const char*)(x + (size_t)bn * 4096) + l * 128;
#pragma unroll
                for (int i = 0; i < 4; i++)
                    asm volatile("prefetch.global.L2 [%0];" :: "l"(pf + i * 4096));
            }
        }

        float blog0 = 0.f, blog1 = 0.f;   // logits for rows rA, rA+32
        float e0 = 0.f, e1 = 0.f;         // own unnormalized exps

#pragma unroll
        for (int it = 0; it < 3; it++) {
            // ---- s-phase (in-lane) ----
            float s0, s1;
            if (it == 0) {
                float a0 = 0.f, a1 = 0.f, c0 = 0.f, c1 = 0.f;
#pragma unroll
                for (int n = 0; n < 64; n += 2) {
                    a0 += xc[n].x;     a1 += xc[n].y;
                    c0 += xc[n + 1].x; c1 += xc[n + 1].y;
                }
                s0 = (a0 + c0) * (1.0f / 64.0f);
                s1 = (a1 + c1) * (1.0f / 64.0f);
            } else {
                float zl = e0 + e1;                    // Z over all 64 rows
#pragma unroll
                for (int off = 16; off > 0; off >>= 1)
                    zl += __shfl_xor_sync(FULLMASK, zl, off);
                const float zinv = frcp(zl);
                float p0 = 0.f, p1 = 0.f, q0 = 0.f, q1 = 0.f;
                const float4* __restrict__ c4 = reinterpret_cast<const float4*>(sew);
#pragma unroll
                for (int m = 0; m < 16; m++) {
                    float4 c = c4[m];                  // broadcast LDS.128
                    p0 = fmaf(c.x, xc[4 * m].x, p0);     p1 = fmaf(c.x, xc[4 * m].y, p1);
                    q0 = fmaf(c.y, xc[4 * m + 1].x, q0); q1 = fmaf(c.y, xc[4 * m + 1].y, q1);
                    p0 = fmaf(c.z, xc[4 * m + 2].x, p0); p1 = fmaf(c.z, xc[4 * m + 2].y, p1);
                    q0 = fmaf(c.w, xc[4 * m + 3].x, q0); q1 = fmaf(c.w, xc[4 * m + 3].y, q1);
                }
                s0 = (p0 + q0) * zinv;
                s1 = (p1 + q1) * zinv;
            }

            // ---- squash scale: nq = |s|^2 via 5-shfl warp reduce ----
            float nq = s0 * s0 + s1 * s1;
#pragma unroll
            for (int off = 16; off > 0; off >>= 1)
                nq += __shfl_xor_sync(FULLMASK, nq, off);
            const float rn    = frsq(nq + 1e-20f);
            const float nrm   = nq * rn;                       // sqrt(nq)
            const float scale = nq * frcp((1.0f + nq) * (nrm + 1e-8f));

            if (it == 2) {   // ---- final: write v ----
                *reinterpret_cast<float2*>(out + (size_t)b * 64 + 2 * l) =
                    make_float2(s0 * scale, s1 * scale);
                break;
            }

            // ---- agreement: two half-butterflies (peak red[16] live) ----
            float ag[2];
#pragma unroll
            for (int h = 0; h < 2; h++) {
                const int base = 32 * h;
                float red[16];
                {
                    const bool hi = l & 1;
#pragma unroll
                    for (int i = 0; i < 16; i++) {
                        float t0 = fmaf(xc[base + i].y,      s1, xc[base + i].x      * s0);
                        float t1 = fmaf(xc[base + i + 16].y, s1, xc[base + i + 16].x * s0);
                        float send = hi ? t0 : t1;
                        float recv = __shfl_xor_sync(FULLMASK, send, 1);
                        red[i] = (hi ? t1 : t0) + recv;
                    }
                }
#pragma unroll
                for (int k = 1; k < 5; k++) {
                    const int half = 16 >> k;
                    const bool hb = (l >> k) & 1;
#pragma unroll
                    for (int i = 0; i < half; i++) {
                        float send = hb ? red[i] : red[i + half];
                        float recv = __shfl_xor_sync(FULLMASK, send, 1 << k);
                        red[i] = (hb ? red[i + half] : red[i]) + recv;
                    }
                }
                ag[h] = red[0];        // full dot for row base + rA
            }
            blog0 += ag[0] * scale;
            blog1 += ag[1] * scale;
            e0 = __expf(blog0);
            e1 = __expf(blog1);
            __syncwarp();              // all lanes' se reads (s-phase) done
            sew[rA]      = e0;
            sew[rA + 32] = e1;
            __syncwarp();              // se visible for next s-phase
        }
    }
}

extern "C" void kernel_launch(void* const* d_in, const int* in_sizes, int n_in,
                              void* d_out, int out_size)
{
    const float* x = (const float*)d_in[0];
    float* out = (float*)d_out;
    const int B = in_sizes[0] / 4096;
    int grid = 148 * 3;                // persistent: 3 CTAs/SM, 12 warps/SM
    if (grid * 4 > B) grid = (B + 3) / 4;
    routing_kernel<<<grid, 128>>>(x, out, B);
}

// round 16
// speedup vs baseline: 1.0165x; 1.0165x over previous
#include <cuda_runtime.h>
#include <cstddef>
#include <cstdint>

// RoutingByAgreement: x[B,64,64] f32 -> v[B,64] f32, 3 iterations.
// TWO-WARP PAIR per batch. 128-thread CTAs, 4 CTAs/SM -> 16 warps/SM,
// 8 independent batch streams per SM. No __syncthreads; pair-local
// named barriers (bar.sync id,64) only.
// Warp h of a pair owns rows 32h..32h+31, lane l owns cols 2l,2l+1:
// float2 xc[32] (64 regs). s-phase partials exchanged through smem;
// agreement is a pure intra-warp 32-row butterfly. Z published per half
// with parity double-buffering. End-of-batch barrier fences the final
// sp2 read against the next batch's first sp2 write (race fix).

#define FULLMASK 0xffffffffu

static __device__ __forceinline__ float frcp(float x) {
    float r; asm("rcp.approx.f32 %0, %1;" : "=f"(r) : "f"(x)); return r;
}
static __device__ __forceinline__ float frsq(float x) {
    float r; asm("rsqrt.approx.f32 %0, %1;" : "=f"(r) : "f"(x)); return r;
}
static __device__ __forceinline__ void barpair(int id) {
    asm volatile("bar.sync %0, 64;" :: "r"(id) : "memory");
}

__global__ void __launch_bounds__(128, 4)
routing_kernel(const float* __restrict__ x, float* __restrict__ out, int B)
{
    __shared__ __align__(16) float  se[2][64];       // [pair][row] exp weights
    __shared__ __align__(16) float2 sp2[2][2][32];   // [pair][half][lane] s partial
    __shared__ float zh[2][2][2];                    // [pair][parity][half] Z half

    const int t = threadIdx.x;
    const int wid = t >> 5, l = t & 31;
    const int p = wid >> 1, h = wid & 1;
    const int barid = 1 + p;

    // butterfly output row within this warp's 32: rA = bitrev5(l)
    const int rA = ((l & 1) << 4) | ((l & 2) << 2) | (l & 4)
                 | ((l & 8) >> 2) | ((l & 16) >> 4);
    const int myrow = h * 32 + rA;

    const int gp = blockIdx.x * 2 + p;       // global pair index
    const int npairs = gridDim.x * 2;

    for (int b = gp; b < B; b += npairs) {
        const float* __restrict__ xb = x + (size_t)b * 4096 + h * 2048 + 2 * l;

        // ---- load this warp's half tile: 32 coalesced LDG.64 ----
        float2 xc[32];
#pragma unroll
        for (int n = 0; n < 32; n++)
            xc[n] = *reinterpret_cast<const float2*>(xb + n * 64);

        // ---- prefetch next batch's half into L2 (2 x 128B lines/lane) ----
        {
            const int bn = b + npairs;
            if (bn < B) {
                const char* pf =
                    (const char*)(x + (size_t)bn * 4096 + h * 2048) + l * 128;
                asm volatile("prefetch.global.L2 [%0];" :: "l"(pf));
                asm volatile("prefetch.global.L2 [%0];" :: "l"(pf + 4096));
            }
        }

        float blog = 0.f;                    // logit for row myrow

#pragma unroll
        for (int it = 0; it < 3; it++) {
            // ---- s-phase partial over own 32 rows (in-lane) ----
            float p0, p1;
            if (it == 0) {
                float a0 = 0.f, a1 = 0.f, c0 = 0.f, c1 = 0.f;
#pragma unroll
                for (int n = 0; n < 32; n += 2) {
                    a0 += xc[n].x;     a1 += xc[n].y;
                    c0 += xc[n + 1].x; c1 += xc[n + 1].y;
                }
                p0 = a0 + c0; p1 = a1 + c1;
            } else {
                float u0 = 0.f, u1 = 0.f, w0 = 0.f, w1 = 0.f;
                const float4* __restrict__ c4 =
                    reinterpret_cast<const float4*>(&se[p][h * 32]);
#pragma unroll
                for (int m = 0; m < 8; m++) {
                    float4 c = c4[m];        // broadcast LDS.128
                    u0 = fmaf(c.x, xc[4 * m].x, u0);     u1 = fmaf(c.x, xc[4 * m].y, u1);
                    w0 = fmaf(c.y, xc[4 * m + 1].x, w0); w1 = fmaf(c.y, xc[4 * m + 1].y, w1);
                    u0 = fmaf(c.z, xc[4 * m + 2].x, u0); u1 = fmaf(c.z, xc[4 * m + 2].y, u1);
                    w0 = fmaf(c.w, xc[4 * m + 3].x, w0); w1 = fmaf(c.w, xc[4 * m + 3].y, w1);
                }
                p0 = u0 + w0; p1 = u1 + w1;
            }
            sp2[p][h][l] = make_float2(p0, p1);
            barpair(barid);                  // C-bar: partials + prev se reads done

            // ---- combine halves; normalize ----
            float2 o = sp2[p][h ^ 1][l];
            float zinv;
            if (it == 0) zinv = 1.0f / 64.0f;
            else {
                const int par = (it + 1) & 1;        // parity written last iter
                zinv = frcp(zh[p][par][0] + zh[p][par][1]);
            }
            float s0 = (p0 + o.x) * zinv;
            float s1 = (p1 + o.y) * zinv;

            // ---- squash scale ----
            float nq = s0 * s0 + s1 * s1;
#pragma unroll
            for (int off = 16; off > 0; off >>= 1)
                nq += __shfl_xor_sync(FULLMASK, nq, off);
            const float rn    = frsq(nq + 1e-20f);
            const float nrm   = nq * rn;
            const float scale = nq * frcp((1.0f + nq) * (nrm + 1e-8f));

            if (it == 2) {                   // ---- final write (warp 0 of pair) ----
                if (h == 0)
                    *reinterpret_cast<float2*>(out + (size_t)b * 64 + 2 * l) =
                        make_float2(s0 * scale, s1 * scale);
                break;
            }

            // ---- agreement: intra-warp butterfly over own 32 rows ----
            float red[16];
            {
                const bool hi = l & 1;
#pragma unroll
                for (int i = 0; i < 16; i++) {
                    float t0 = fmaf(xc[i].y,      s1, xc[i].x      * s0);
                    float t1 = fmaf(xc[i + 16].y, s1, xc[i + 16].x * s0);
                    float send = hi ? t0 : t1;
                    float recv = __shfl_xor_sync(FULLMASK, send, 1);
                    red[i] = (hi ? t1 : t0) + recv;
                }
            }
#pragma unroll
            for (int k = 1; k < 5; k++) {
                const int half = 16 >> k;
                const bool hb = (l >> k) & 1;
#pragma unroll
                for (int i = 0; i < half; i++) {
                    float send = hb ? red[i] : red[i + half];
                    float recv = __shfl_xor_sync(FULLMASK, send, 1 << k);
                    red[i] = (hb ? red[i + half] : red[i]) + recv;
                }
            }
            blog += red[0] * scale;          // full dot for row myrow
            const float e = __expf(blog);

            // Z half for next iteration + weight publish
            float zs = e;
#pragma unroll
            for (int off = 16; off > 0; off >>= 1)
                zs += __shfl_xor_sync(FULLMASK, zs, off);
            if (l == 0) zh[p][it & 1][h] = zs;
            se[p][myrow] = e;                // permutation-indexed, conflict-free
            barpair(barid);                  // G-bar: se/zh visible; WAR fences
        }

        barpair(barid);                      // batch-end: fence final sp2 read
                                             // against next batch's sp2 write
    }
}

extern "C" void kernel_launch(void* const* d_in, const int* in_sizes, int n_in,
                              void* d_out, int out_size)
{
    const float* x = (const float*)d_in[0];
    float* out = (float*)d_out;
    const int B = in_sizes[0] / 4096;
    int grid = 148 * 4;                // 4 CTAs/SM, 2 pairs/CTA -> 8 streams/SM
    if (grid * 2 > B) grid = (B + 1) / 2;
    routing_kernel<<<grid, 128>>>(x, out, B);
}